// round 6
// baseline (speedup 1.0000x reference)
#include <cuda_runtime.h>

// 7-level db4 DWT -> soft threshold -> IDWT, fully fused in SMEM.
// One CTA per row; dense vector LDS/LDG (R4 pattern); scalar FFMA-imm math.
// R6: tiny levels executed redundantly by ALL warps into a dedicated arena
//     (benign identical-value races), removing the idle window + one barrier.

#define NTHREADS 128
#define NROWS    32768
#define N0       1116

static __constant__ float DLO[8] = {
    -0.010597401784997278f,  0.032883011666982945f,  0.030841381835986965f,
    -0.18703481171888114f,  -0.02798376941698385f,   0.6308807679295904f,
     0.7148465705525415f,    0.23037781330885523f
};
static __constant__ float DHI[8] = {
    -0.23037781330885523f,   0.7148465705525415f,   -0.6308807679295904f,
    -0.02798376941698385f,   0.18703481171888114f,   0.030841381835986965f,
    -0.032883011666982945f, -0.010597401784997278f
};

__device__ __forceinline__ float softf(float c, float t) {
    return copysignf(fmaxf(fabsf(c) - t, 0.0f), c);
}

// ---- forward level 1: read row directly from gmem (zero-extended).
template<int NTH>
__device__ __forceinline__ void fwd_gmem(const float* __restrict__ x,
                                         float* __restrict__ an,
                                         float* __restrict__ dph,
                                         float thr, int tid)
{
    constexpr int M   = 561;
    constexpr int PAD = (M + 1) / 2 + 8;   // 289
    for (int t = tid; t < PAD; t += NTH) {
        float r[16];
        const int b0 = 4 * t - 8;
        #pragma unroll
        for (int bi = 0; bi < 4; bi++) {
            const int idx = b0 + 4 * bi;
            float4 v = make_float4(0.f, 0.f, 0.f, 0.f);
            if (idx >= 0 && idx + 4 <= N0) v = *(const float4*)(x + idx);
            *(float4*)(r + 4 * bi) = v;
        }
        float ca0 = 0.f, cd0 = 0.f, ca1 = 0.f, cd1 = 0.f;
        #pragma unroll
        for (int k = 0; k < 8; k++) {
            ca0 = fmaf(r[2 + k], DLO[7 - k], ca0);
            cd0 = fmaf(r[2 + k], DHI[7 - k], cd0);
            ca1 = fmaf(r[4 + k], DLO[7 - k], ca1);
            cd1 = fmaf(r[4 + k], DHI[7 - k], cd1);
        }
        cd0 = softf(cd0, thr); cd1 = softf(cd1, thr);
        const int j0 = 2 * t;
        *(float2*)(an + 6 + j0) = make_float2(j0 < M ? ca0 : 0.f,
                                              (j0 + 1) < M ? ca1 : 0.f);
        if (j0 < M)
            *(float2*)(dph + j0) = make_float2(cd0, (j0 + 1) < M ? cd1 : 0.f);
    }
}

// ---- forward SMEM level, 2 outputs/unit, dense 16B-stride LDS.128.
template<int M, bool LAST, int NTH>
__device__ __forceinline__ void fwd_level(const float* __restrict__ a,
                                          float* __restrict__ an,
                                          float* __restrict__ dph,
                                          float thr, int tid)
{
    constexpr int PAD = (M + 1) / 2 + 8;
    for (int t = tid; t < PAD; t += NTH) {
        float r[12];
        *(float4*)(r)     = *(const float4*)(a + 4 * t);
        *(float4*)(r + 4) = *(const float4*)(a + 4 * t + 4);
        *(float4*)(r + 8) = *(const float4*)(a + 4 * t + 8);
        float ca0 = 0.f, cd0 = 0.f, ca1 = 0.f, cd1 = 0.f;
        #pragma unroll
        for (int k = 0; k < 8; k++) {
            ca0 = fmaf(r[k],     DLO[7 - k], ca0);
            cd0 = fmaf(r[k],     DHI[7 - k], cd0);
            ca1 = fmaf(r[k + 2], DLO[7 - k], ca1);
            cd1 = fmaf(r[k + 2], DHI[7 - k], cd1);
        }
        cd0 = softf(cd0, thr); cd1 = softf(cd1, thr);
        if (LAST) { ca0 = softf(ca0, thr); ca1 = softf(ca1, thr); }
        const int j0 = 2 * t;
        *(float2*)(an + 6 + j0) = make_float2(j0 < M ? ca0 : 0.f,
                                              (j0 + 1) < M ? ca1 : 0.f);
        if (j0 < M)
            *(float2*)(dph + j0) = make_float2(cd0, (j0 + 1) < M ? cd1 : 0.f);
    }
}

// ---- inverse level, 4 outputs/unit, dense 8B-stride loads, 16B stores.
template<int MD, int NTH>
__device__ __forceinline__ void inv_level(const float* __restrict__ a,
                                          const float* __restrict__ d,
                                          float* __restrict__ o, int tid)
{
    constexpr int OLEN  = 2 * MD - 6;
    constexpr int QUADS = (OLEN + 3) / 4;
    for (int u = tid; u < QUADS; u += NTH) {
        const int s = 2 * u;
        const float2 a01 = *(const float2*)(a + s);
        const float2 a23 = *(const float2*)(a + s + 2);
        const float  a4  = a[s + 4];
        const float2 d01 = *(const float2*)(d + s);
        const float2 d23 = *(const float2*)(d + s + 2);
        const float  d4  = d[s + 4];
        float o0 = a01.x * DLO[1];  o0 = fmaf(a01.y, DLO[3], o0);
        o0 = fmaf(a23.x, DLO[5], o0); o0 = fmaf(a23.y, DLO[7], o0);
        o0 = fmaf(d01.x, DHI[1], o0); o0 = fmaf(d01.y, DHI[3], o0);
        o0 = fmaf(d23.x, DHI[5], o0); o0 = fmaf(d23.y, DHI[7], o0);
        float o1 = a01.x * DLO[0];  o1 = fmaf(a01.y, DLO[2], o1);
        o1 = fmaf(a23.x, DLO[4], o1); o1 = fmaf(a23.y, DLO[6], o1);
        o1 = fmaf(d01.x, DHI[0], o1); o1 = fmaf(d01.y, DHI[2], o1);
        o1 = fmaf(d23.x, DHI[4], o1); o1 = fmaf(d23.y, DHI[6], o1);
        float o2 = a01.y * DLO[1];  o2 = fmaf(a23.x, DLO[3], o2);
        o2 = fmaf(a23.y, DLO[5], o2); o2 = fmaf(a4,   DLO[7], o2);
        o2 = fmaf(d01.y, DHI[1], o2); o2 = fmaf(d23.x, DHI[3], o2);
        o2 = fmaf(d23.y, DHI[5], o2); o2 = fmaf(d4,   DHI[7], o2);
        float o3 = a01.y * DLO[0];  o3 = fmaf(a23.x, DLO[2], o3);
        o3 = fmaf(a23.y, DLO[4], o3); o3 = fmaf(a4,   DLO[6], o3);
        o3 = fmaf(d01.y, DHI[0], o3); o3 = fmaf(d23.x, DHI[2], o3);
        o3 = fmaf(d23.y, DHI[4], o3); o3 = fmaf(d4,   DHI[6], o3);
        if (4 * u + 3 < OLEN) *(float4*)(o + 4 * u) = make_float4(o0, o1, o2, o3);
        else                  *(float2*)(o + 4 * u) = make_float2(o0, o1);
    }
}

__global__ __launch_bounds__(NTHREADS)
void wavelet_fused_kernel(const float* __restrict__ x,
                          const float* __restrict__ rawthr,
                          float* __restrict__ out)
{
    // Level lengths: {1116, 561, 284, 145, 76, 41, 24, 15}
    __shared__ __align__(16) float sA[1168];
    __shared__ __align__(16) float sB[640];
    __shared__ __align__(16) float sD[1152];  // doff: 0,562,846,992,1068,1110,1134
    // tiny-level arena: disjoint regions, each address written with one value
    // only -> cross-warp redundant execution is race-benign.
    __shared__ __align__(16) float sT[384];
    float* const T41 = sT + 0;     // fwd41 approx out  (writes [6,64), reads to 92)
    float* const T24 = sT + 96;    // fwd24 approx out  (writes [6,46), reads to 72)
    float* const T15 = sT + 176;   // fwd15 approx out  (writes [6,38))
    float* const I15 = sT + 224;   // inv15 out, len 24 (+overshoot read 24)
    float* const I24 = sT + 256;   // inv24 out, len 42 (+overshoot)
    float* const I41 = sT + 304;   // inv41 out, len 76 (+overshoot read 76)

    const int row  = blockIdx.x;
    const int tid  = threadIdx.x;
    const int lane = tid & 31;
    const float thr = fmaxf(__ldg(rawthr), 0.01f);
    const float* __restrict__ xr = x + (size_t)row * N0;

    // residual zero-fill (never overwritten before their reads)
    if (tid < 6) { sA[tid] = 0.f; sB[tid] = 0.f;
                   T41[tid] = 0.f; T24[tid] = 0.f; T15[tid] = 0.f; }
    if (tid >= 64 && tid < 64 + 56) sB[520 + tid] = 0.f;   // sB[584..640)
    __syncthreads();

    // ---- forward DWT (level 1 straight from gmem)
    fwd_gmem<NTHREADS>(xr, sB, sD + 0, thr, tid);                 __syncthreads();
    fwd_level<284, false, NTHREADS>(sB, sA, sD + 562, thr, tid);  __syncthreads();
    fwd_level<145, false, NTHREADS>(sA, sB, sD + 846, thr, tid);  __syncthreads();
    fwd_level<76,  false, NTHREADS>(sB, sA, sD + 992, thr, tid);  __syncthreads();

    // ---- tiny levels: every warp runs the full pipeline redundantly into the
    // arena (identical values; __syncwarp orders within-warp SMEM deps). Each
    // warp ends owning a complete I41, so no __syncthreads before inv<76>.
    fwd_level<41, false, 32>(sA,  T41, sD + 1068, thr, lane); __syncwarp();
    fwd_level<24, false, 32>(T41, T24, sD + 1110, thr, lane); __syncwarp();
    fwd_level<15, true,  32>(T24, T15, sD + 1134, thr, lane); __syncwarp();
    inv_level<15, 32>(T15 + 6, sD + 1134, I15, lane);         __syncwarp();
    inv_level<24, 32>(I15,     sD + 1110, I24, lane);         __syncwarp();
    inv_level<41, 32>(I24,     sD + 1068, I41, lane);         __syncwarp();

    // ---- inverse DWT, big levels; final level streams to gmem
    inv_level<76,  NTHREADS>(I41,    sD + 992, sB + 8, tid); __syncthreads();
    inv_level<145, NTHREADS>(sB + 8, sD + 846, sA + 8, tid); __syncthreads();
    inv_level<284, NTHREADS>(sA + 8, sD + 562, sB + 8, tid); __syncthreads();
    inv_level<561, NTHREADS>(sB + 8, sD + 0, out + (size_t)row * N0, tid);
}

extern "C" void kernel_launch(void* const* d_in, const int* in_sizes, int n_in,
                              void* d_out, int out_size)
{
    const float* x    = (const float*)d_in[0];
    const float* rthr = (const float*)d_in[1];
    float* out        = (float*)d_out;
    wavelet_fused_kernel<<<NROWS, NTHREADS>>>(x, rthr, out);
}

// round 7
// speedup vs baseline: 1.2045x; 1.2045x over previous
#include <cuda_runtime.h>

// 7-level db4 DWT -> soft threshold -> IDWT, fully fused in SMEM.
// One CTA per row. R7 = R4 + dense 8-wide inverse units (fewer LDS/STS)
// + unpredicated interior loads in the gmem-direct forward level.

#define NTHREADS 128
#define NROWS    32768
#define N0       1116

static __constant__ float DLO[8] = {
    -0.010597401784997278f,  0.032883011666982945f,  0.030841381835986965f,
    -0.18703481171888114f,  -0.02798376941698385f,   0.6308807679295904f,
     0.7148465705525415f,    0.23037781330885523f
};
static __constant__ float DHI[8] = {
    -0.23037781330885523f,   0.7148465705525415f,   -0.6308807679295904f,
    -0.02798376941698385f,   0.18703481171888114f,   0.030841381835986965f,
    -0.032883011666982945f, -0.010597401784997278f
};

__device__ __forceinline__ float softf(float c, float t) {
    return copysignf(fmaxf(fabsf(c) - t, 0.0f), c);
}

// ---- forward level 1: read row directly from gmem (zero-extended).
// Interior units (t in [2,278)) take an unpredicated fast path.
template<int NTH>
__device__ __forceinline__ void fwd_gmem(const float* __restrict__ x,
                                         float* __restrict__ an,
                                         float* __restrict__ dph,
                                         float thr, int tid)
{
    constexpr int M   = 561;
    constexpr int PAD = (M + 1) / 2 + 8;   // 289
    for (int t = tid; t < PAD; t += NTH) {
        float r[16];
        const int b0 = 4 * t - 8;
        if (t >= 2 && t < 278) {
            #pragma unroll
            for (int bi = 0; bi < 4; bi++)
                *(float4*)(r + 4 * bi) = *(const float4*)(x + b0 + 4 * bi);
        } else {
            #pragma unroll
            for (int bi = 0; bi < 4; bi++) {
                const int idx = b0 + 4 * bi;
                float4 v = make_float4(0.f, 0.f, 0.f, 0.f);
                if (idx >= 0 && idx + 4 <= N0) v = *(const float4*)(x + idx);
                *(float4*)(r + 4 * bi) = v;
            }
        }
        float ca0 = 0.f, cd0 = 0.f, ca1 = 0.f, cd1 = 0.f;
        #pragma unroll
        for (int k = 0; k < 8; k++) {
            ca0 = fmaf(r[2 + k], DLO[7 - k], ca0);
            cd0 = fmaf(r[2 + k], DHI[7 - k], cd0);
            ca1 = fmaf(r[4 + k], DLO[7 - k], ca1);
            cd1 = fmaf(r[4 + k], DHI[7 - k], cd1);
        }
        cd0 = softf(cd0, thr); cd1 = softf(cd1, thr);
        const int j0 = 2 * t;
        *(float2*)(an + 6 + j0) = make_float2(j0 < M ? ca0 : 0.f,
                                              (j0 + 1) < M ? ca1 : 0.f);
        if (j0 < M)
            *(float2*)(dph + j0) = make_float2(cd0, (j0 + 1) < M ? cd1 : 0.f);
    }
}

// ---- forward SMEM level, 2 outputs/unit, dense 16B-stride LDS.128.
template<int M, bool LAST, int NTH>
__device__ __forceinline__ void fwd_level(const float* __restrict__ a,
                                          float* __restrict__ an,
                                          float* __restrict__ dph,
                                          float thr, int tid)
{
    constexpr int PAD = (M + 1) / 2 + 8;
    for (int t = tid; t < PAD; t += NTH) {
        float r[12];
        *(float4*)(r)     = *(const float4*)(a + 4 * t);
        *(float4*)(r + 4) = *(const float4*)(a + 4 * t + 4);
        *(float4*)(r + 8) = *(const float4*)(a + 4 * t + 8);
        float ca0 = 0.f, cd0 = 0.f, ca1 = 0.f, cd1 = 0.f;
        #pragma unroll
        for (int k = 0; k < 8; k++) {
            ca0 = fmaf(r[k],     DLO[7 - k], ca0);
            cd0 = fmaf(r[k],     DHI[7 - k], cd0);
            ca1 = fmaf(r[k + 2], DLO[7 - k], ca1);
            cd1 = fmaf(r[k + 2], DHI[7 - k], cd1);
        }
        cd0 = softf(cd0, thr); cd1 = softf(cd1, thr);
        if (LAST) { ca0 = softf(ca0, thr); ca1 = softf(ca1, thr); }
        const int j0 = 2 * t;
        *(float2*)(an + 6 + j0) = make_float2(j0 < M ? ca0 : 0.f,
                                              (j0 + 1) < M ? ca1 : 0.f);
        if (j0 < M)
            *(float2*)(dph + j0) = make_float2(cd0, (j0 + 1) < M ? cd1 : 0.f);
    }
}

// ---- inverse level, 4 outputs/unit (tiny levels only).
template<int MD, int NTH>
__device__ __forceinline__ void inv4(const float* __restrict__ a,
                                     const float* __restrict__ d,
                                     float* __restrict__ o, int tid)
{
    constexpr int OLEN  = 2 * MD - 6;
    constexpr int QUADS = (OLEN + 3) / 4;
    for (int u = tid; u < QUADS; u += NTH) {
        const int s = 2 * u;
        const float2 a01 = *(const float2*)(a + s);
        const float2 a23 = *(const float2*)(a + s + 2);
        const float  a4  = a[s + 4];
        const float2 d01 = *(const float2*)(d + s);
        const float2 d23 = *(const float2*)(d + s + 2);
        const float  d4  = d[s + 4];
        float o0 = a01.x * DLO[1];  o0 = fmaf(a01.y, DLO[3], o0);
        o0 = fmaf(a23.x, DLO[5], o0); o0 = fmaf(a23.y, DLO[7], o0);
        o0 = fmaf(d01.x, DHI[1], o0); o0 = fmaf(d01.y, DHI[3], o0);
        o0 = fmaf(d23.x, DHI[5], o0); o0 = fmaf(d23.y, DHI[7], o0);
        float o1 = a01.x * DLO[0];  o1 = fmaf(a01.y, DLO[2], o1);
        o1 = fmaf(a23.x, DLO[4], o1); o1 = fmaf(a23.y, DLO[6], o1);
        o1 = fmaf(d01.x, DHI[0], o1); o1 = fmaf(d01.y, DHI[2], o1);
        o1 = fmaf(d23.x, DHI[4], o1); o1 = fmaf(d23.y, DHI[6], o1);
        float o2 = a01.y * DLO[1];  o2 = fmaf(a23.x, DLO[3], o2);
        o2 = fmaf(a23.y, DLO[5], o2); o2 = fmaf(a4,   DLO[7], o2);
        o2 = fmaf(d01.y, DHI[1], o2); o2 = fmaf(d23.x, DHI[3], o2);
        o2 = fmaf(d23.y, DHI[5], o2); o2 = fmaf(d4,   DHI[7], o2);
        float o3 = a01.y * DLO[0];  o3 = fmaf(a23.x, DLO[2], o3);
        o3 = fmaf(a23.y, DLO[4], o3); o3 = fmaf(a4,   DLO[6], o3);
        o3 = fmaf(d01.y, DHI[0], o3); o3 = fmaf(d23.x, DHI[2], o3);
        o3 = fmaf(d23.y, DHI[4], o3); o3 = fmaf(d4,   DHI[6], o3);
        if (4 * u + 3 < OLEN) *(float4*)(o + 4 * u) = make_float4(o0, o1, o2, o3);
        else                  *(float2*)(o + 4 * u) = make_float2(o0, o1);
    }
}

// ---- inverse level, 8 outputs/unit, dense float4 loads/stores; o may be gmem.
template<int MD, int NTH>
__device__ __forceinline__ void inv8(const float* __restrict__ a,
                                     const float* __restrict__ d,
                                     float* __restrict__ o, int tid)
{
    constexpr int OLEN  = 2 * MD - 6;
    constexpr int UNITS = (OLEN + 7) / 8;
    for (int w = tid; w < UNITS; w += NTH) {
        float A[8], D[8];
        *(float4*)(A)     = *(const float4*)(a + 4 * w);
        *(float4*)(A + 4) = *(const float4*)(a + 4 * w + 4);
        *(float4*)(D)     = *(const float4*)(d + 4 * w);
        *(float4*)(D + 4) = *(const float4*)(d + 4 * w + 4);
        float o8[8];
        #pragma unroll
        for (int p = 0; p < 4; p++) {
            float e = 0.f, f = 0.f;
            #pragma unroll
            for (int j = 0; j < 4; j++) {
                e = fmaf(A[p + j], DLO[2 * j + 1], e);
                e = fmaf(D[p + j], DHI[2 * j + 1], e);
                f = fmaf(A[p + j], DLO[2 * j],     f);
                f = fmaf(D[p + j], DHI[2 * j],     f);
            }
            o8[2 * p] = e; o8[2 * p + 1] = f;
        }
        const int t0 = 8 * w;
        if (t0 + 7 < OLEN) {
            *(float4*)(o + t0)     = make_float4(o8[0], o8[1], o8[2], o8[3]);
            *(float4*)(o + t0 + 4) = make_float4(o8[4], o8[5], o8[6], o8[7]);
        } else {
            const int rem = OLEN - t0;   // 2 or 4 for our levels
            if (rem >= 4) {
                *(float4*)(o + t0) = make_float4(o8[0], o8[1], o8[2], o8[3]);
                if (rem == 6) *(float2*)(o + t0 + 4) = make_float2(o8[4], o8[5]);
            } else {
                *(float2*)(o + t0) = make_float2(o8[0], o8[1]);
            }
        }
    }
}

__global__ __launch_bounds__(NTHREADS)
void wavelet_fused_kernel(const float* __restrict__ x,
                          const float* __restrict__ rawthr,
                          float* __restrict__ out)
{
    // Level lengths: {1116, 561, 284, 145, 76, 41, 24, 15}
    __shared__ __align__(16) float sA[1168];
    __shared__ __align__(16) float sB[640];
    __shared__ __align__(16) float sD[1160]; // doff (16B-aligned): 0,564,848,996,1072,1116,1140

    const int row = blockIdx.x;
    const int tid = threadIdx.x;
    const float thr = fmaxf(__ldg(rawthr), 0.01f);
    const float* __restrict__ xr = x + (size_t)row * N0;

    // residual zero-fill (regions never overwritten before their reads)
    if (tid < 6)       { sA[tid] = 0.f; sB[tid] = 0.f; }
    if (tid >= 64 && tid < 64 + 56) sB[520 + tid] = 0.f;   // sB[584..640)
    __syncthreads();

    // ---- forward DWT (level 1 straight from gmem)
    fwd_gmem<NTHREADS>(xr, sB, sD + 0, thr, tid);                 __syncthreads();
    fwd_level<284, false, NTHREADS>(sB, sA, sD + 564, thr, tid);  __syncthreads();
    fwd_level<145, false, NTHREADS>(sA, sB, sD + 848, thr, tid);  __syncthreads();
    fwd_level<76,  false, NTHREADS>(sB, sA, sD + 996, thr, tid);  __syncthreads();

    // ---- tiny levels: single warp, __syncwarp only
    if (tid < 32) {
        fwd_level<41, false, 32>(sA, sB, sD + 1072, thr, tid); __syncwarp();
        fwd_level<24, false, 32>(sB, sA, sD + 1116, thr, tid); __syncwarp();
        fwd_level<15, true,  32>(sA, sB, sD + 1140, thr, tid); __syncwarp();
        inv4<15, 32>(sB + 6, sD + 1140, sA + 8, tid);          __syncwarp();
        inv4<24, 32>(sA + 8, sD + 1116, sB + 8, tid);          __syncwarp();
        inv4<41, 32>(sB + 8, sD + 1072, sA + 8, tid);
    }
    __syncthreads();

    // ---- inverse DWT, big levels; final level streams to gmem
    inv8<76,  NTHREADS>(sA + 8, sD + 996, sB + 8, tid); __syncthreads();
    inv8<145, NTHREADS>(sB + 8, sD + 848, sA + 8, tid); __syncthreads();
    inv8<284, NTHREADS>(sA + 8, sD + 564, sB + 8, tid); __syncthreads();
    inv8<561, NTHREADS>(sB + 8, sD + 0, out + (size_t)row * N0, tid);
}

extern "C" void kernel_launch(void* const* d_in, const int* in_sizes, int n_in,
                              void* d_out, int out_size)
{
    const float* x    = (const float*)d_in[0];
    const float* rthr = (const float*)d_in[1];
    float* out        = (float*)d_out;
    wavelet_fused_kernel<<<NROWS, NTHREADS>>>(x, rthr, out);
}

// round 8
// speedup vs baseline: 1.2239x; 1.0161x over previous
#include <cuda_runtime.h>

// 7-level db4 DWT -> soft threshold -> IDWT, fully fused in SMEM.
// R8: TWO independent rows per CTA (64 threads each) — halves per-row barrier
// overhead and doubles work-units-per-thread on the small levels.

#define NTHREADS 128
#define RPT      2           // rows per CTA
#define NROWS    32768
#define N0       1116

static __constant__ float DLO[8] = {
    -0.010597401784997278f,  0.032883011666982945f,  0.030841381835986965f,
    -0.18703481171888114f,  -0.02798376941698385f,   0.6308807679295904f,
     0.7148465705525415f,    0.23037781330885523f
};
static __constant__ float DHI[8] = {
    -0.23037781330885523f,   0.7148465705525415f,   -0.6308807679295904f,
    -0.02798376941698385f,   0.18703481171888114f,   0.030841381835986965f,
    -0.032883011666982945f, -0.010597401784997278f
};

__device__ __forceinline__ float softf(float c, float t) {
    return copysignf(fmaxf(fabsf(c) - t, 0.0f), c);
}

// ---- forward level 1: read row directly from gmem (zero-extended).
template<int NTH>
__device__ __forceinline__ void fwd_gmem(const float* __restrict__ x,
                                         float* __restrict__ an,
                                         float* __restrict__ dph,
                                         float thr, int tid)
{
    constexpr int M   = 561;
    constexpr int PAD = (M + 1) / 2 + 8;   // 289
    for (int t = tid; t < PAD; t += NTH) {
        float r[16];
        const int b0 = 4 * t - 8;
        if (t >= 2 && t < 278) {
            #pragma unroll
            for (int bi = 0; bi < 4; bi++)
                *(float4*)(r + 4 * bi) = *(const float4*)(x + b0 + 4 * bi);
        } else {
            #pragma unroll
            for (int bi = 0; bi < 4; bi++) {
                const int idx = b0 + 4 * bi;
                float4 v = make_float4(0.f, 0.f, 0.f, 0.f);
                if (idx >= 0 && idx + 4 <= N0) v = *(const float4*)(x + idx);
                *(float4*)(r + 4 * bi) = v;
            }
        }
        float ca0 = 0.f, cd0 = 0.f, ca1 = 0.f, cd1 = 0.f;
        #pragma unroll
        for (int k = 0; k < 8; k++) {
            ca0 = fmaf(r[2 + k], DLO[7 - k], ca0);
            cd0 = fmaf(r[2 + k], DHI[7 - k], cd0);
            ca1 = fmaf(r[4 + k], DLO[7 - k], ca1);
            cd1 = fmaf(r[4 + k], DHI[7 - k], cd1);
        }
        cd0 = softf(cd0, thr); cd1 = softf(cd1, thr);
        const int j0 = 2 * t;
        *(float2*)(an + 6 + j0) = make_float2(j0 < M ? ca0 : 0.f,
                                              (j0 + 1) < M ? ca1 : 0.f);
        if (j0 < M)
            *(float2*)(dph + j0) = make_float2(cd0, (j0 + 1) < M ? cd1 : 0.f);
    }
}

// ---- forward SMEM level, 2 outputs/unit, dense 16B-stride LDS.128.
template<int M, bool LAST, int NTH>
__device__ __forceinline__ void fwd_level(const float* __restrict__ a,
                                          float* __restrict__ an,
                                          float* __restrict__ dph,
                                          float thr, int tid)
{
    constexpr int PAD = (M + 1) / 2 + 8;
    for (int t = tid; t < PAD; t += NTH) {
        float r[12];
        *(float4*)(r)     = *(const float4*)(a + 4 * t);
        *(float4*)(r + 4) = *(const float4*)(a + 4 * t + 4);
        *(float4*)(r + 8) = *(const float4*)(a + 4 * t + 8);
        float ca0 = 0.f, cd0 = 0.f, ca1 = 0.f, cd1 = 0.f;
        #pragma unroll
        for (int k = 0; k < 8; k++) {
            ca0 = fmaf(r[k],     DLO[7 - k], ca0);
            cd0 = fmaf(r[k],     DHI[7 - k], cd0);
            ca1 = fmaf(r[k + 2], DLO[7 - k], ca1);
            cd1 = fmaf(r[k + 2], DHI[7 - k], cd1);
        }
        cd0 = softf(cd0, thr); cd1 = softf(cd1, thr);
        if (LAST) { ca0 = softf(ca0, thr); ca1 = softf(ca1, thr); }
        const int j0 = 2 * t;
        *(float2*)(an + 6 + j0) = make_float2(j0 < M ? ca0 : 0.f,
                                              (j0 + 1) < M ? ca1 : 0.f);
        if (j0 < M)
            *(float2*)(dph + j0) = make_float2(cd0, (j0 + 1) < M ? cd1 : 0.f);
    }
}

// ---- inverse level, 4 outputs/unit (tiny levels only).
template<int MD, int NTH>
__device__ __forceinline__ void inv4(const float* __restrict__ a,
                                     const float* __restrict__ d,
                                     float* __restrict__ o, int tid)
{
    constexpr int OLEN  = 2 * MD - 6;
    constexpr int QUADS = (OLEN + 3) / 4;
    for (int u = tid; u < QUADS; u += NTH) {
        const int s = 2 * u;
        const float2 a01 = *(const float2*)(a + s);
        const float2 a23 = *(const float2*)(a + s + 2);
        const float  a4  = a[s + 4];
        const float2 d01 = *(const float2*)(d + s);
        const float2 d23 = *(const float2*)(d + s + 2);
        const float  d4  = d[s + 4];
        float o0 = a01.x * DLO[1];  o0 = fmaf(a01.y, DLO[3], o0);
        o0 = fmaf(a23.x, DLO[5], o0); o0 = fmaf(a23.y, DLO[7], o0);
        o0 = fmaf(d01.x, DHI[1], o0); o0 = fmaf(d01.y, DHI[3], o0);
        o0 = fmaf(d23.x, DHI[5], o0); o0 = fmaf(d23.y, DHI[7], o0);
        float o1 = a01.x * DLO[0];  o1 = fmaf(a01.y, DLO[2], o1);
        o1 = fmaf(a23.x, DLO[4], o1); o1 = fmaf(a23.y, DLO[6], o1);
        o1 = fmaf(d01.x, DHI[0], o1); o1 = fmaf(d01.y, DHI[2], o1);
        o1 = fmaf(d23.x, DHI[4], o1); o1 = fmaf(d23.y, DHI[6], o1);
        float o2 = a01.y * DLO[1];  o2 = fmaf(a23.x, DLO[3], o2);
        o2 = fmaf(a23.y, DLO[5], o2); o2 = fmaf(a4,   DLO[7], o2);
        o2 = fmaf(d01.y, DHI[1], o2); o2 = fmaf(d23.x, DHI[3], o2);
        o2 = fmaf(d23.y, DHI[5], o2); o2 = fmaf(d4,   DHI[7], o2);
        float o3 = a01.y * DLO[0];  o3 = fmaf(a23.x, DLO[2], o3);
        o3 = fmaf(a23.y, DLO[4], o3); o3 = fmaf(a4,   DLO[6], o3);
        o3 = fmaf(d01.y, DHI[0], o3); o3 = fmaf(d23.x, DHI[2], o3);
        o3 = fmaf(d23.y, DHI[4], o3); o3 = fmaf(d4,   DHI[6], o3);
        if (4 * u + 3 < OLEN) *(float4*)(o + 4 * u) = make_float4(o0, o1, o2, o3);
        else                  *(float2*)(o + 4 * u) = make_float2(o0, o1);
    }
}

// ---- inverse level, 8 outputs/unit, dense float4 loads/stores; o may be gmem.
template<int MD, int NTH>
__device__ __forceinline__ void inv8(const float* __restrict__ a,
                                     const float* __restrict__ d,
                                     float* __restrict__ o, int tid)
{
    constexpr int OLEN  = 2 * MD - 6;
    constexpr int UNITS = (OLEN + 7) / 8;
    for (int w = tid; w < UNITS; w += NTH) {
        float A[8], D[8];
        *(float4*)(A)     = *(const float4*)(a + 4 * w);
        *(float4*)(A + 4) = *(const float4*)(a + 4 * w + 4);
        *(float4*)(D)     = *(const float4*)(d + 4 * w);
        *(float4*)(D + 4) = *(const float4*)(d + 4 * w + 4);
        float o8[8];
        #pragma unroll
        for (int p = 0; p < 4; p++) {
            float e = 0.f, f = 0.f;
            #pragma unroll
            for (int j = 0; j < 4; j++) {
                e = fmaf(A[p + j], DLO[2 * j + 1], e);
                e = fmaf(D[p + j], DHI[2 * j + 1], e);
                f = fmaf(A[p + j], DLO[2 * j],     f);
                f = fmaf(D[p + j], DHI[2 * j],     f);
            }
            o8[2 * p] = e; o8[2 * p + 1] = f;
        }
        const int t0 = 8 * w;
        if (t0 + 7 < OLEN) {
            *(float4*)(o + t0)     = make_float4(o8[0], o8[1], o8[2], o8[3]);
            *(float4*)(o + t0 + 4) = make_float4(o8[4], o8[5], o8[6], o8[7]);
        } else {
            const int rem = OLEN - t0;   // 2, 4 or 6
            if (rem >= 4) {
                *(float4*)(o + t0) = make_float4(o8[0], o8[1], o8[2], o8[3]);
                if (rem == 6) *(float2*)(o + t0 + 4) = make_float2(o8[4], o8[5]);
            } else {
                *(float2*)(o + t0) = make_float2(o8[0], o8[1]);
            }
        }
    }
}

__global__ __launch_bounds__(NTHREADS)
void wavelet_fused_kernel(const float* __restrict__ x,
                          const float* __restrict__ rawthr,
                          float* __restrict__ out)
{
    // Level lengths: {1116, 561, 284, 145, 76, 41, 24, 15}
    // Per-row buffers; 2 independent rows per CTA.
    __shared__ __align__(16) float sA[RPT][1168];
    __shared__ __align__(16) float sB[RPT][640];
    __shared__ __align__(16) float sD[RPT][1160]; // doff: 0,564,848,996,1072,1116,1140

    const int tid  = threadIdx.x;
    const int half = tid >> 6;          // which row within the CTA
    const int rtid = tid & 63;          // thread id within the row team (64)
    const int row  = blockIdx.x * RPT + half;
    const float thr = fmaxf(__ldg(rawthr), 0.01f);

    float* const pA = sA[half];
    float* const pB = sB[half];
    float* const pD = sD[half];
    const float* __restrict__ xr = x + (size_t)row * N0;
    float* __restrict__ outr     = out + (size_t)row * N0;

    // residual zero-fill (regions never overwritten before their reads)
    if (rtid < 6)  { pA[rtid] = 0.f; pB[rtid] = 0.f; }
    if (rtid < 56) pB[584 + rtid] = 0.f;
    __syncthreads();

    // ---- forward DWT (level 1 straight from gmem)
    fwd_gmem<64>(xr, pB, pD + 0, thr, rtid);                 __syncthreads();
    fwd_level<284, false, 64>(pB, pA, pD + 564, thr, rtid);  __syncthreads();
    fwd_level<145, false, 64>(pA, pB, pD + 848, thr, rtid);  __syncthreads();
    fwd_level<76,  false, 64>(pB, pA, pD + 996, thr, rtid);  __syncthreads();

    // ---- tiny levels: one warp per row (warps 0 and 2), __syncwarp only
    if (rtid < 32) {
        fwd_level<41, false, 32>(pA, pB, pD + 1072, thr, rtid); __syncwarp();
        fwd_level<24, false, 32>(pB, pA, pD + 1116, thr, rtid); __syncwarp();
        fwd_level<15, true,  32>(pA, pB, pD + 1140, thr, rtid); __syncwarp();
        inv4<15, 32>(pB + 6, pD + 1140, pA + 8, rtid);          __syncwarp();
        inv4<24, 32>(pA + 8, pD + 1116, pB + 8, rtid);          __syncwarp();
        inv4<41, 32>(pB + 8, pD + 1072, pA + 8, rtid);
    }
    __syncthreads();

    // ---- inverse DWT, big levels; final level streams to gmem
    inv8<76,  64>(pA + 8, pD + 996, pB + 8, rtid); __syncthreads();
    inv8<145, 64>(pB + 8, pD + 848, pA + 8, rtid); __syncthreads();
    inv8<284, 64>(pA + 8, pD + 564, pB + 8, rtid); __syncthreads();
    inv8<561, 64>(pB + 8, pD + 0, outr, rtid);
}

extern "C" void kernel_launch(void* const* d_in, const int* in_sizes, int n_in,
                              void* d_out, int out_size)
{
    const float* x    = (const float*)d_in[0];
    const float* rthr = (const float*)d_in[1];
    float* out        = (float*)d_out;
    wavelet_fused_kernel<<<NROWS / RPT, NTHREADS>>>(x, rthr, out);
}

// round 9
// speedup vs baseline: 1.2549x; 1.0253x over previous
#include <cuda_runtime.h>

// 7-level db4 DWT -> soft threshold -> IDWT, fused in SMEM.
// R9: each CTA (128 threads) processes TWO rows, interleaved inside every
// unit body -> 2x ILP/MLP per thread, half the barriers per row, full-width
// teams at every level. Tiny levels: warp0 = row0, warp1 = row1.

#define NTHREADS 128
#define RPT      2
#define NROWS    32768
#define N0       1116

static __constant__ float DLO[8] = {
    -0.010597401784997278f,  0.032883011666982945f,  0.030841381835986965f,
    -0.18703481171888114f,  -0.02798376941698385f,   0.6308807679295904f,
     0.7148465705525415f,    0.23037781330885523f
};
static __constant__ float DHI[8] = {
    -0.23037781330885523f,   0.7148465705525415f,   -0.6308807679295904f,
    -0.02798376941698385f,   0.18703481171888114f,   0.030841381835986965f,
    -0.032883011666982945f, -0.010597401784997278f
};

__device__ __forceinline__ float softf(float c, float t) {
    return copysignf(fmaxf(fabsf(c) - t, 0.0f), c);
}

// ---- dual-row forward level 1 from gmem (zero-extended reads).
template<int NTH>
__device__ __forceinline__ void fwd_gmem2(const float* __restrict__ x0,
                                          const float* __restrict__ x1,
                                          float* __restrict__ an0, float* __restrict__ an1,
                                          float* __restrict__ dp0, float* __restrict__ dp1,
                                          float thr, int tid)
{
    constexpr int M   = 561;
    constexpr int PAD = 289;
    for (int t = tid; t < PAD; t += NTH) {
        float r0[16], r1[16];
        const int b0 = 4 * t - 8;
        if (t >= 2 && t < 278) {
            #pragma unroll
            for (int bi = 0; bi < 4; bi++) {
                *(float4*)(r0 + 4 * bi) = *(const float4*)(x0 + b0 + 4 * bi);
                *(float4*)(r1 + 4 * bi) = *(const float4*)(x1 + b0 + 4 * bi);
            }
        } else {
            #pragma unroll
            for (int bi = 0; bi < 4; bi++) {
                const int idx = b0 + 4 * bi;
                float4 v0 = make_float4(0.f, 0.f, 0.f, 0.f), v1 = v0;
                if (idx >= 0 && idx + 4 <= N0) {
                    v0 = *(const float4*)(x0 + idx);
                    v1 = *(const float4*)(x1 + idx);
                }
                *(float4*)(r0 + 4 * bi) = v0;
                *(float4*)(r1 + 4 * bi) = v1;
            }
        }
        float a00 = 0.f, d00 = 0.f, a01 = 0.f, d01 = 0.f;
        float a10 = 0.f, d10 = 0.f, a11 = 0.f, d11 = 0.f;
        #pragma unroll
        for (int k = 0; k < 8; k++) {
            a00 = fmaf(r0[2 + k], DLO[7 - k], a00); d00 = fmaf(r0[2 + k], DHI[7 - k], d00);
            a01 = fmaf(r0[4 + k], DLO[7 - k], a01); d01 = fmaf(r0[4 + k], DHI[7 - k], d01);
            a10 = fmaf(r1[2 + k], DLO[7 - k], a10); d10 = fmaf(r1[2 + k], DHI[7 - k], d10);
            a11 = fmaf(r1[4 + k], DLO[7 - k], a11); d11 = fmaf(r1[4 + k], DHI[7 - k], d11);
        }
        d00 = softf(d00, thr); d01 = softf(d01, thr);
        d10 = softf(d10, thr); d11 = softf(d11, thr);
        const int j0 = 2 * t;
        const bool v0ok = j0 < M, v1ok = (j0 + 1) < M;
        *(float2*)(an0 + 6 + j0) = make_float2(v0ok ? a00 : 0.f, v1ok ? a01 : 0.f);
        *(float2*)(an1 + 6 + j0) = make_float2(v0ok ? a10 : 0.f, v1ok ? a11 : 0.f);
        if (v0ok) {
            *(float2*)(dp0 + j0) = make_float2(d00, v1ok ? d01 : 0.f);
            *(float2*)(dp1 + j0) = make_float2(d10, v1ok ? d11 : 0.f);
        }
    }
}

// ---- dual-row forward SMEM level, 2 outputs/unit/row.
template<int M, int NTH>
__device__ __forceinline__ void fwd_level2(const float* __restrict__ a0,
                                           const float* __restrict__ a1,
                                           float* __restrict__ an0, float* __restrict__ an1,
                                           float* __restrict__ dp0, float* __restrict__ dp1,
                                           float thr, int tid)
{
    constexpr int PAD = (M + 1) / 2 + 8;
    for (int t = tid; t < PAD; t += NTH) {
        float r0[12], r1[12];
        *(float4*)(r0)     = *(const float4*)(a0 + 4 * t);
        *(float4*)(r0 + 4) = *(const float4*)(a0 + 4 * t + 4);
        *(float4*)(r0 + 8) = *(const float4*)(a0 + 4 * t + 8);
        *(float4*)(r1)     = *(const float4*)(a1 + 4 * t);
        *(float4*)(r1 + 4) = *(const float4*)(a1 + 4 * t + 4);
        *(float4*)(r1 + 8) = *(const float4*)(a1 + 4 * t + 8);
        float a00 = 0.f, d00 = 0.f, a01 = 0.f, d01 = 0.f;
        float a10 = 0.f, d10 = 0.f, a11 = 0.f, d11 = 0.f;
        #pragma unroll
        for (int k = 0; k < 8; k++) {
            a00 = fmaf(r0[k],     DLO[7 - k], a00); d00 = fmaf(r0[k],     DHI[7 - k], d00);
            a01 = fmaf(r0[k + 2], DLO[7 - k], a01); d01 = fmaf(r0[k + 2], DHI[7 - k], d01);
            a10 = fmaf(r1[k],     DLO[7 - k], a10); d10 = fmaf(r1[k],     DHI[7 - k], d10);
            a11 = fmaf(r1[k + 2], DLO[7 - k], a11); d11 = fmaf(r1[k + 2], DHI[7 - k], d11);
        }
        d00 = softf(d00, thr); d01 = softf(d01, thr);
        d10 = softf(d10, thr); d11 = softf(d11, thr);
        const int j0 = 2 * t;
        const bool v0ok = j0 < M, v1ok = (j0 + 1) < M;
        *(float2*)(an0 + 6 + j0) = make_float2(v0ok ? a00 : 0.f, v1ok ? a01 : 0.f);
        *(float2*)(an1 + 6 + j0) = make_float2(v0ok ? a10 : 0.f, v1ok ? a11 : 0.f);
        if (v0ok) {
            *(float2*)(dp0 + j0) = make_float2(d00, v1ok ? d01 : 0.f);
            *(float2*)(dp1 + j0) = make_float2(d10, v1ok ? d11 : 0.f);
        }
    }
}

// ---- single-row forward SMEM level (tiny levels, one warp per row)
template<int M, bool LAST>
__device__ __forceinline__ void fwd_level(const float* __restrict__ a,
                                          float* __restrict__ an,
                                          float* __restrict__ dph,
                                          float thr, int tid)
{
    constexpr int PAD = (M + 1) / 2 + 8;
    for (int t = tid; t < PAD; t += 32) {
        float r[12];
        *(float4*)(r)     = *(const float4*)(a + 4 * t);
        *(float4*)(r + 4) = *(const float4*)(a + 4 * t + 4);
        *(float4*)(r + 8) = *(const float4*)(a + 4 * t + 8);
        float ca0 = 0.f, cd0 = 0.f, ca1 = 0.f, cd1 = 0.f;
        #pragma unroll
        for (int k = 0; k < 8; k++) {
            ca0 = fmaf(r[k],     DLO[7 - k], ca0);
            cd0 = fmaf(r[k],     DHI[7 - k], cd0);
            ca1 = fmaf(r[k + 2], DLO[7 - k], ca1);
            cd1 = fmaf(r[k + 2], DHI[7 - k], cd1);
        }
        cd0 = softf(cd0, thr); cd1 = softf(cd1, thr);
        if (LAST) { ca0 = softf(ca0, thr); ca1 = softf(ca1, thr); }
        const int j0 = 2 * t;
        *(float2*)(an + 6 + j0) = make_float2(j0 < M ? ca0 : 0.f,
                                              (j0 + 1) < M ? ca1 : 0.f);
        if (j0 < M)
            *(float2*)(dph + j0) = make_float2(cd0, (j0 + 1) < M ? cd1 : 0.f);
    }
}

// ---- single-row inverse, 4 outputs/unit (tiny levels)
template<int MD>
__device__ __forceinline__ void inv4(const float* __restrict__ a,
                                     const float* __restrict__ d,
                                     float* __restrict__ o, int tid)
{
    constexpr int OLEN  = 2 * MD - 6;
    constexpr int QUADS = (OLEN + 3) / 4;
    for (int u = tid; u < QUADS; u += 32) {
        const int s = 2 * u;
        const float2 a01 = *(const float2*)(a + s);
        const float2 a23 = *(const float2*)(a + s + 2);
        const float  a4  = a[s + 4];
        const float2 d01 = *(const float2*)(d + s);
        const float2 d23 = *(const float2*)(d + s + 2);
        const float  d4  = d[s + 4];
        float o0 = a01.x * DLO[1];  o0 = fmaf(a01.y, DLO[3], o0);
        o0 = fmaf(a23.x, DLO[5], o0); o0 = fmaf(a23.y, DLO[7], o0);
        o0 = fmaf(d01.x, DHI[1], o0); o0 = fmaf(d01.y, DHI[3], o0);
        o0 = fmaf(d23.x, DHI[5], o0); o0 = fmaf(d23.y, DHI[7], o0);
        float o1 = a01.x * DLO[0];  o1 = fmaf(a01.y, DLO[2], o1);
        o1 = fmaf(a23.x, DLO[4], o1); o1 = fmaf(a23.y, DLO[6], o1);
        o1 = fmaf(d01.x, DHI[0], o1); o1 = fmaf(d01.y, DHI[2], o1);
        o1 = fmaf(d23.x, DHI[4], o1); o1 = fmaf(d23.y, DHI[6], o1);
        float o2 = a01.y * DLO[1];  o2 = fmaf(a23.x, DLO[3], o2);
        o2 = fmaf(a23.y, DLO[5], o2); o2 = fmaf(a4,   DLO[7], o2);
        o2 = fmaf(d01.y, DHI[1], o2); o2 = fmaf(d23.x, DHI[3], o2);
        o2 = fmaf(d23.y, DHI[5], o2); o2 = fmaf(d4,   DHI[7], o2);
        float o3 = a01.y * DLO[0];  o3 = fmaf(a23.x, DLO[2], o3);
        o3 = fmaf(a23.y, DLO[4], o3); o3 = fmaf(a4,   DLO[6], o3);
        o3 = fmaf(d01.y, DHI[0], o3); o3 = fmaf(d23.x, DHI[2], o3);
        o3 = fmaf(d23.y, DHI[4], o3); o3 = fmaf(d4,   DHI[6], o3);
        if (4 * u + 3 < OLEN) *(float4*)(o + 4 * u) = make_float4(o0, o1, o2, o3);
        else                  *(float2*)(o + 4 * u) = make_float2(o0, o1);
    }
}

// ---- dual-row inverse, 8 outputs/unit/row; outputs may be gmem.
template<int MD, int NTH>
__device__ __forceinline__ void inv8_2(const float* __restrict__ a0,
                                       const float* __restrict__ a1,
                                       const float* __restrict__ d0,
                                       const float* __restrict__ d1,
                                       float* __restrict__ o0, float* __restrict__ o1,
                                       int tid)
{
    constexpr int OLEN  = 2 * MD - 6;
    constexpr int UNITS = (OLEN + 7) / 8;
    for (int w = tid; w < UNITS; w += NTH) {
        float A0[8], D0[8], A1[8], D1[8];
        *(float4*)(A0)     = *(const float4*)(a0 + 4 * w);
        *(float4*)(A0 + 4) = *(const float4*)(a0 + 4 * w + 4);
        *(float4*)(D0)     = *(const float4*)(d0 + 4 * w);
        *(float4*)(D0 + 4) = *(const float4*)(d0 + 4 * w + 4);
        *(float4*)(A1)     = *(const float4*)(a1 + 4 * w);
        *(float4*)(A1 + 4) = *(const float4*)(a1 + 4 * w + 4);
        *(float4*)(D1)     = *(const float4*)(d1 + 4 * w);
        *(float4*)(D1 + 4) = *(const float4*)(d1 + 4 * w + 4);
        float s0[8], s1[8];
        #pragma unroll
        for (int p = 0; p < 4; p++) {
            float e0 = 0.f, f0 = 0.f, e1 = 0.f, f1 = 0.f;
            #pragma unroll
            for (int j = 0; j < 4; j++) {
                e0 = fmaf(A0[p + j], DLO[2 * j + 1], e0);
                e0 = fmaf(D0[p + j], DHI[2 * j + 1], e0);
                f0 = fmaf(A0[p + j], DLO[2 * j],     f0);
                f0 = fmaf(D0[p + j], DHI[2 * j],     f0);
                e1 = fmaf(A1[p + j], DLO[2 * j + 1], e1);
                e1 = fmaf(D1[p + j], DHI[2 * j + 1], e1);
                f1 = fmaf(A1[p + j], DLO[2 * j],     f1);
                f1 = fmaf(D1[p + j], DHI[2 * j],     f1);
            }
            s0[2 * p] = e0; s0[2 * p + 1] = f0;
            s1[2 * p] = e1; s1[2 * p + 1] = f1;
        }
        const int t0 = 8 * w;
        if (t0 + 7 < OLEN) {
            *(float4*)(o0 + t0)     = make_float4(s0[0], s0[1], s0[2], s0[3]);
            *(float4*)(o0 + t0 + 4) = make_float4(s0[4], s0[5], s0[6], s0[7]);
            *(float4*)(o1 + t0)     = make_float4(s1[0], s1[1], s1[2], s1[3]);
            *(float4*)(o1 + t0 + 4) = make_float4(s1[4], s1[5], s1[6], s1[7]);
        } else {
            const int rem = OLEN - t0;   // 2, 4 or 6
            if (rem >= 4) {
                *(float4*)(o0 + t0) = make_float4(s0[0], s0[1], s0[2], s0[3]);
                *(float4*)(o1 + t0) = make_float4(s1[0], s1[1], s1[2], s1[3]);
                if (rem == 6) {
                    *(float2*)(o0 + t0 + 4) = make_float2(s0[4], s0[5]);
                    *(float2*)(o1 + t0 + 4) = make_float2(s1[4], s1[5]);
                }
            } else {
                *(float2*)(o0 + t0) = make_float2(s0[0], s0[1]);
                *(float2*)(o1 + t0) = make_float2(s1[0], s1[1]);
            }
        }
    }
}

__global__ __launch_bounds__(NTHREADS, 8)
void wavelet_fused_kernel(const float* __restrict__ x,
                          const float* __restrict__ rawthr,
                          float* __restrict__ out)
{
    // Level lengths: {1116, 561, 284, 145, 76, 41, 24, 15}
    __shared__ __align__(16) float sA[RPT][1168];
    __shared__ __align__(16) float sB[RPT][640];
    __shared__ __align__(16) float sD[RPT][1160]; // doff: 0,564,848,996,1072,1116,1140

    const int tid = threadIdx.x;
    const int row0 = blockIdx.x * RPT;
    const float thr = fmaxf(__ldg(rawthr), 0.01f);

    float* const A0 = sA[0]; float* const A1 = sA[1];
    float* const B0 = sB[0]; float* const B1 = sB[1];
    float* const D0 = sD[0]; float* const D1 = sD[1];
    const float* __restrict__ x0 = x + (size_t)row0 * N0;
    const float* __restrict__ x1 = x0 + N0;
    float* __restrict__ o0 = out + (size_t)row0 * N0;
    float* __restrict__ o1 = o0 + N0;

    // residual zero-fill (regions never overwritten before their reads)
    if (tid < 6)  { A0[tid] = 0.f; A1[tid] = 0.f; B0[tid] = 0.f; B1[tid] = 0.f; }
    if (tid < 56) { B0[584 + tid] = 0.f; B1[584 + tid] = 0.f; }
    __syncthreads();

    // ---- forward DWT (level 1 straight from gmem), dual-row
    fwd_gmem2<NTHREADS>(x0, x1, B0, B1, D0 + 0, D1 + 0, thr, tid);          __syncthreads();
    fwd_level2<284, NTHREADS>(B0, B1, A0, A1, D0 + 564, D1 + 564, thr, tid); __syncthreads();
    fwd_level2<145, NTHREADS>(A0, A1, B0, B1, D0 + 848, D1 + 848, thr, tid); __syncthreads();
    fwd_level2<76,  NTHREADS>(B0, B1, A0, A1, D0 + 996, D1 + 996, thr, tid); __syncthreads();

    // ---- tiny levels: warp 0 -> row 0, warp 1 -> row 1 (parallel, warp-sync)
    if (tid < 64) {
        const int lane = tid & 31;
        float* pA = (tid < 32) ? A0 : A1;
        float* pB = (tid < 32) ? B0 : B1;
        float* pD = (tid < 32) ? D0 : D1;
        fwd_level<41, false>(pA, pB, pD + 1072, thr, lane); __syncwarp();
        fwd_level<24, false>(pB, pA, pD + 1116, thr, lane); __syncwarp();
        fwd_level<15, true >(pA, pB, pD + 1140, thr, lane); __syncwarp();
        inv4<15>(pB + 6, pD + 1140, pA + 8, lane);          __syncwarp();
        inv4<24>(pA + 8, pD + 1116, pB + 8, lane);          __syncwarp();
        inv4<41>(pB + 8, pD + 1072, pA + 8, lane);
    }
    __syncthreads();

    // ---- inverse DWT, big levels, dual-row; final level streams to gmem
    inv8_2<76,  NTHREADS>(A0 + 8, A1 + 8, D0 + 996, D1 + 996, B0 + 8, B1 + 8, tid); __syncthreads();
    inv8_2<145, NTHREADS>(B0 + 8, B1 + 8, D0 + 848, D1 + 848, A0 + 8, A1 + 8, tid); __syncthreads();
    inv8_2<284, NTHREADS>(A0 + 8, A1 + 8, D0 + 564, D1 + 564, B0 + 8, B1 + 8, tid); __syncthreads();
    inv8_2<561, NTHREADS>(B0 + 8, B1 + 8, D0 + 0,   D1 + 0,   o0,     o1,     tid);
}

extern "C" void kernel_launch(void* const* d_in, const int* in_sizes, int n_in,
                              void* d_out, int out_size)
{
    const float* x    = (const float*)d_in[0];
    const float* rthr = (const float*)d_in[1];
    float* out        = (float*)d_out;
    wavelet_fused_kernel<<<NROWS / RPT, NTHREADS>>>(x, rthr, out);
}